// round 4
// baseline (speedup 1.0000x reference)
#include <cuda_runtime.h>
#include <cuda_bf16.h>
#include <math.h>

// Problem shape (fixed by setup_inputs)
#define RB  16
#define RT  200
#define RU  100
#define RU1 101
#define RV  512
#define NEGV (-1e30f)

// Scratch (device globals; no allocation allowed)
__device__ float g_blank[RB * RT * RU1];
__device__ float g_emit [RB * RT * RU1];
__device__ float g_costs[RB];

// ---------------------------------------------------------------------------
// Kernel 1: per-(b,t,u) log-softmax -> blank_lp and emit_lp.
// One warp per row of V=512. Single pass: 16 floats/lane in registers.
// Memory-bound by design: reads 662 MB of acts exactly once, coalesced.
// ---------------------------------------------------------------------------
__global__ __launch_bounds__(256, 8)
void rnnt_lse_kernel(const float* __restrict__ acts,
                     const int*   __restrict__ labels,
                     const int*   __restrict__ label_lens)
{
    const int rows = RB * RT * RU1;
    int warp = (blockIdx.x * blockDim.x + threadIdx.x) >> 5;
    int lane = threadIdx.x & 31;
    if (warp >= rows) return;

    long long base = (long long)warp * RV;
    const float4* p = (const float4*)(acts + base);

    float4 v0 = p[lane +  0];
    float4 v1 = p[lane + 32];
    float4 v2 = p[lane + 64];
    float4 v3 = p[lane + 96];

    float m = fmaxf(fmaxf(fmaxf(v0.x, v0.y), fmaxf(v0.z, v0.w)),
                    fmaxf(fmaxf(v1.x, v1.y), fmaxf(v1.z, v1.w)));
    m = fmaxf(m, fmaxf(fmaxf(fmaxf(v2.x, v2.y), fmaxf(v2.z, v2.w)),
                       fmaxf(fmaxf(v3.x, v3.y), fmaxf(v3.z, v3.w))));
    #pragma unroll
    for (int o = 16; o; o >>= 1) m = fmaxf(m, __shfl_xor_sync(0xffffffffu, m, o));

    float s = 0.f;
    s += expf(v0.x - m) + expf(v0.y - m) + expf(v0.z - m) + expf(v0.w - m);
    s += expf(v1.x - m) + expf(v1.y - m) + expf(v1.z - m) + expf(v1.w - m);
    s += expf(v2.x - m) + expf(v2.y - m) + expf(v2.z - m) + expf(v2.w - m);
    s += expf(v3.x - m) + expf(v3.y - m) + expf(v3.z - m) + expf(v3.w - m);
    #pragma unroll
    for (int o = 16; o; o >>= 1) s += __shfl_xor_sync(0xffffffffu, s, o);

    if (lane == 0) {
        float lse = m + logf(s);
        int u  = warp % RU1;
        int b  = warp / (RU1 * RT);
        g_blank[warp] = acts[base] - lse;          // class 0 = BLANK
        float e = NEGV;
        if (u < label_lens[b]) {                   // label_len <= RU=100 < RU1, so u < RU here
            int lab = labels[b * RU + u];          // lab in [1, V)
            e = acts[base + lab] - lse;
        }
        g_emit[warp] = e;
    }
}

// ---------------------------------------------------------------------------
// Kernel 2: anti-diagonal wavefront over the (T, U+1) lattice.
// One CTA per batch item; 128 threads; double-buffered alpha diag in SMEM;
// operands for the next diagonal prefetched (clamped indices, branchless).
// ---------------------------------------------------------------------------
__device__ __forceinline__ float laexp(float a, float b)
{
    float m = fmaxf(a, b);
    float n = fminf(a, b);
    return m + log1pf(expf(n - m));
}

__global__ __launch_bounds__(128, 1)
void rnnt_alpha_kernel(const int* __restrict__ act_lens,
                       const int* __restrict__ label_lens)
{
    const int b = blockIdx.x;
    const int u = threadIdx.x;            // threads 0..RU1-1 do work; rest only barrier
    const float* __restrict__ blank = g_blank + b * RT * RU1;
    const float* __restrict__ emit  = g_emit  + b * RT * RU1;
    const int aT = act_lens[b];
    const int L  = label_lens[b];

    __shared__ float sbuf[2][RU1];
    int p = 0;

    float bl_next = NEGV, em_next = NEGV;

    for (int d = 0; d < RT + RU1 - 1; ++d) {
        const int t = d - u;
        const float bl = bl_next, em = em_next;

        // Prefetch operands needed at diagonal d+1 (where this thread sees t+1).
        // Indices are clamped into range; out-of-range cells never consume them.
        if (u < RU1) {
            int tn  = t + 1;
            int tnc = min(max(tn, 0), RT - 1);
            int tbc = min(max(tn - 1, 0), RT - 1);
            int upc = (u > 0) ? (u - 1) : 0;
            bl_next = blank[tbc * RU1 + u];        // used when tn>=1 (valid then)
            em_next = emit [tnc * RU1 + upc];      // used when u>=1 && tn in range
        }

        if (u < RU1 && t >= 0 && t < RT) {
            float a;
            if (t == 0 && u == 0) {
                a = 0.f;
            } else {
                float noemit = (t >= 1) ? (sbuf[p][u]     + bl) : NEGV;
                float emitv  = (u >= 1) ? (sbuf[p][u - 1] + em) : NEGV;
                a = laexp(noemit, emitv);
            }
            sbuf[p ^ 1][u] = a;
            if (t == aT - 1 && u == L) {
                g_costs[b] = -(a + blank[t * RU1 + u]);
            }
        }
        __syncthreads();
        p ^= 1;
    }
}

// ---------------------------------------------------------------------------
// Kernel 3: deterministic fixed-order reduction of per-batch costs.
// ---------------------------------------------------------------------------
__global__ void rnnt_reduce_kernel(float* __restrict__ out)
{
    if (threadIdx.x == 0) {
        float s = 0.f;
        #pragma unroll
        for (int b = 0; b < RB; ++b) s += g_costs[b];
        out[0] = s * (1.0f / RB);
    }
}

extern "C" void kernel_launch(void* const* d_in, const int* in_sizes, int n_in,
                              void* d_out, int out_size)
{
    const float* acts       = (const float*)d_in[0];
    const int*   labels     = (const int*)  d_in[1];
    const int*   act_lens   = (const int*)  d_in[2];
    const int*   label_lens = (const int*)  d_in[3];
    float*       out        = (float*)      d_out;

    const int rows = RB * RT * RU1;                 // 323200 rows, 1 warp each
    const int threads = 256;                        // 8 warps / block
    const int blocks = (rows + 7) / 8;

    rnnt_lse_kernel<<<blocks, threads>>>(acts, labels, label_lens);
    rnnt_alpha_kernel<<<RB, 128>>>(act_lens, label_lens);
    rnnt_reduce_kernel<<<1, 32>>>(out);
}

// round 5
// speedup vs baseline: 1.3331x; 1.3331x over previous
#include <cuda_runtime.h>
#include <cuda_bf16.h>
#include <math.h>

// Problem shape (fixed by setup_inputs)
#define RB  16
#define RT  200
#define RU  100
#define RU1 101
#define RV  512
#define NEGV (-1e30f)

// Scratch (device globals; no allocation allowed)
__device__ float g_blank[RB * RT * RU1];
__device__ float g_emit [RB * RT * RU1];
__device__ float g_costs[RB];
__device__ int   g_arrive = 0;   // self-resetting arrival counter (graph-replay safe)

// ---------------------------------------------------------------------------
// Kernel 1: per-(b,t,u) log-softmax -> blank_lp and emit_lp.
// One warp per row of V=512; 16 floats/lane in registers; MUFU-based exp/log
// so the kernel stays HBM-bound (reads 662 MB exactly once, coalesced).
// ---------------------------------------------------------------------------
__global__ __launch_bounds__(256, 8)
void rnnt_lse_kernel(const float* __restrict__ acts,
                     const int*   __restrict__ labels,
                     const int*   __restrict__ label_lens)
{
    int warp = (blockIdx.x * blockDim.x + threadIdx.x) >> 5;
    int lane = threadIdx.x & 31;

    long long base = (long long)warp * RV;
    const float4* p = (const float4*)(acts + base);

    float4 v0 = p[lane +  0];
    float4 v1 = p[lane + 32];
    float4 v2 = p[lane + 64];
    float4 v3 = p[lane + 96];

    float m = fmaxf(fmaxf(fmaxf(v0.x, v0.y), fmaxf(v0.z, v0.w)),
                    fmaxf(fmaxf(v1.x, v1.y), fmaxf(v1.z, v1.w)));
    m = fmaxf(m, fmaxf(fmaxf(fmaxf(v2.x, v2.y), fmaxf(v2.z, v2.w)),
                       fmaxf(fmaxf(v3.x, v3.y), fmaxf(v3.z, v3.w))));
    #pragma unroll
    for (int o = 16; o; o >>= 1) m = fmaxf(m, __shfl_xor_sync(0xffffffffu, m, o));

    float s = 0.f;
    s += __expf(v0.x - m) + __expf(v0.y - m) + __expf(v0.z - m) + __expf(v0.w - m);
    s += __expf(v1.x - m) + __expf(v1.y - m) + __expf(v1.z - m) + __expf(v1.w - m);
    s += __expf(v2.x - m) + __expf(v2.y - m) + __expf(v2.z - m) + __expf(v2.w - m);
    s += __expf(v3.x - m) + __expf(v3.y - m) + __expf(v3.z - m) + __expf(v3.w - m);
    #pragma unroll
    for (int o = 16; o; o >>= 1) s += __shfl_xor_sync(0xffffffffu, s, o);

    if (lane == 0) {
        float lse = m + __logf(s);
        int u  = warp % RU1;
        int b  = warp / (RU1 * RT);
        g_blank[warp] = v0.x - lse;                // lane0's v0.x == acts[base+0] (BLANK)
        float e = NEGV;
        if (u < label_lens[b]) {                   // label_len <= 100 < RU1
            int lab = labels[b * RU + u];          // in [1, V)
            e = acts[base + lab] - lse;
        }
        g_emit[warp] = e;
    }
}

// ---------------------------------------------------------------------------
// Kernel 2: anti-diagonal wavefront DP + fused final reduction.
// One CTA (128 thr) per batch item; thread u owns lattice column u.
//   - neighbor alpha(u-1, prev diag) via __shfl_up; cross-warp boundary via
//     double-buffered 4-float SMEM slot -> exactly ONE barrier per diagonal
//   - blank/emit operands prefetched 2 diagonals ahead (L2-resident, 2.6 MB)
//   - fast-math logaddexp (EX2/LG2)
//   - last CTA (threadfence-reduction pattern) sums costs deterministically
// ---------------------------------------------------------------------------
__device__ __forceinline__ float laexp(float x, float y)
{
    float m = fmaxf(x, y);
    float d = fabsf(x - y);
    return m + __logf(1.f + __expf(-d));
}

__global__ __launch_bounds__(128, 1)
void rnnt_alpha_kernel(const int* __restrict__ act_lens,
                       const int* __restrict__ label_lens,
                       float* __restrict__ out)
{
    const int b    = blockIdx.x;
    const int tid  = threadIdx.x;
    const int w    = tid >> 5;
    const int lane = tid & 31;
    const int u    = tid;                      // threads 101..127 are passengers
    const int uc   = min(u, RU1 - 1);

    const float* __restrict__ blank = g_blank + b * RT * RU1;
    const float* __restrict__ emit  = g_emit  + b * RT * RU1;
    const int aT   = act_lens[b];
    const int L    = label_lens[b];
    const int dmax = aT - 1 + L;               // diag of terminal cell

    __shared__ float sbnd[2][4];               // per-warp boundary alpha, dbl-buffered

    if (tid < 8) sbnd[tid >> 2][tid & 3] = NEGV;

    // depth-2 operand prefetch: slot k holds (bl, em) for diagonal d with d&1==k
    float blq[2], emq[2];
    #pragma unroll
    for (int k = 0; k < 2; ++k) {
        int t  = k - uc;
        int tb = min(max(t - 1, 0), RT - 1);
        int te = min(max(t,     0), RT - 1);
        blq[k] = blank[tb * RU1 + uc];
        emq[k] = emit [te * RU1 + (uc ? uc - 1 : 0)];
    }

    float a = NEGV;                            // alpha at previous diagonal, this u
    int   p = 0;
    __syncthreads();

    for (int d = 0; d <= dmax; ++d) {
        const int slot = d & 1;
        const float bl = blq[slot], em = emq[slot];

        // issue prefetch for diagonal d+2 immediately (hides L2 latency)
        {
            int t  = d + 2 - uc;
            int tb = min(max(t - 1, 0), RT - 1);
            int te = min(max(t,     0), RT - 1);
            blq[slot] = blank[tb * RU1 + uc];
            emq[slot] = emit [te * RU1 + (uc ? uc - 1 : 0)];
        }

        // alpha(prev diag, u-1): intra-warp shuffle; lane0 from left warp's slot
        float a_left = __shfl_up_sync(0xffffffffu, a, 1);
        if (lane == 0) a_left = (w > 0) ? sbnd[p][w - 1] : NEGV;

        const int t = d - u;
        const bool active = (u < RU1) & (t >= 0) & (t < RT);
        float noemit = (t >= 1) ? (a + bl)      : NEGV;
        float emitv  = (u >= 1) ? (a_left + em) : NEGV;
        float anew = laexp(noemit, emitv);
        if (t == 0 && u == 0) anew = 0.f;

        if (active) {
            a = anew;
            if (t == aT - 1 && u == L)
                g_costs[b] = -(a + blank[t * RU1 + u]);
        }
        if (lane == 31) sbnd[p ^ 1][w] = a;    // publish boundary for next diag
        __syncthreads();
        p ^= 1;
    }

    // fused deterministic reduction (threadfence-reduction pattern)
    __syncthreads();
    if (tid == 0) {
        __threadfence();
        int prev = atomicAdd(&g_arrive, 1);
        if (prev == RB - 1) {
            atomicExch(&g_arrive, 0);          // reset for next graph replay
            __threadfence();
            float s = 0.f;
            #pragma unroll
            for (int i = 0; i < RB; ++i) s += g_costs[i];
            out[0] = s * (1.0f / RB);
        }
    }
}

extern "C" void kernel_launch(void* const* d_in, const int* in_sizes, int n_in,
                              void* d_out, int out_size)
{
    const float* acts       = (const float*)d_in[0];
    const int*   labels     = (const int*)  d_in[1];
    const int*   act_lens   = (const int*)  d_in[2];
    const int*   label_lens = (const int*)  d_in[3];
    float*       out        = (float*)      d_out;

    const int rows   = RB * RT * RU1;              // 323200 rows, 1 warp each
    const int blocks = rows / 8;                   // 8 warps per 256-thr block (exact)

    rnnt_lse_kernel<<<blocks, 256>>>(acts, labels, label_lens);
    rnnt_alpha_kernel<<<RB, 128>>>(act_lens, label_lens, out);
}